// round 16
// baseline (speedup 1.0000x reference)
#include <cuda_runtime.h>
#include <cuda_fp16.h>
#include <cstdint>

// Blockwise int4-dequant GEMM, fp16 mma.sync m16n8k16 + ldmatrix.x4.
// Round 14: 128x128x64 CTA tile, FOUR warps (warp tile 64x64), 2 CTA/SM,
// 3-stage cp.async pipeline, fragment DOUBLE-BUFFERING (ldmatrix for k-step
// kk+1 issued before MMAs of kk). Crossbar/tile = 96KB (768 cyc) vs tensor
// 1024 cyc -> tensor-bound with slack; double-buffer hides LDS latency that
// sank the 4-warp config in R12. Transposed grid for L2 (from R13).
//
// Phase 1: prep A -> fp16, W=(Q-zp)*s -> fp16 (global scratch).

#define M_DIM 4096
#define K_DIM 4096
#define N_DIM 11008

__device__ uint32_t gA[(size_t)M_DIM * K_DIM / 2];   // half2-packed A [M, K/2]
__device__ uint32_t gW[(size_t)N_DIM * K_DIM / 2];   // half2-packed W [N, K/2]

#define BM 128
#define BN 128
#define BK 64                        // k elements per tile (32 half2 words)
#define KW 32                        // words per row per tile
#define SSTRIDE 36                   // words per smem row (32 + 4 pad)
#define STAGES 3
#define STAGE_WORDS ((BM + BN) * SSTRIDE)
#define SMEM_BYTES (STAGES * STAGE_WORDS * 4)
#define NTHREADS 128

__device__ __forceinline__ uint32_t pack_h2(float lo, float hi) {
    uint32_t r;
    asm("{\n\t.reg .f16 l, h;\n\t"
        "cvt.rn.f16.f32 l, %1;\n\t"
        "cvt.rn.f16.f32 h, %2;\n\t"
        "mov.b32 %0, {l, h};\n\t}"
        : "=r"(r) : "f"(lo), "f"(hi));
    return r;
}

__device__ __forceinline__ void mma_f16(float& c0, float& c1, float& c2, float& c3,
                                        uint32_t a0, uint32_t a1, uint32_t a2, uint32_t a3,
                                        uint32_t b0, uint32_t b1) {
    asm volatile("mma.sync.aligned.m16n8k16.row.col.f32.f16.f16.f32 "
                 "{%0,%1,%2,%3}, {%4,%5,%6,%7}, {%8,%9}, {%0,%1,%2,%3};\n"
                 : "+f"(c0), "+f"(c1), "+f"(c2), "+f"(c3)
                 : "r"(a0), "r"(a1), "r"(a2), "r"(a3), "r"(b0), "r"(b1));
}

#define LDSM_X4(r0, r1, r2, r3, addr)                                        \
    asm volatile("ldmatrix.sync.aligned.m8n8.x4.shared.b16 {%0,%1,%2,%3}, [%4];" \
                 : "=r"(r0), "=r"(r1), "=r"(r2), "=r"(r3) : "r"(addr))

#define CP_ASYNC16(dst, src) \
    asm volatile("cp.async.cg.shared.global [%0], [%1], 16;" :: "r"(dst), "l"(src))
#define CP_COMMIT()  asm volatile("cp.async.commit_group;" ::: "memory")
#define CP_WAIT(n)   asm volatile("cp.async.wait_group %0;" :: "n"(n) : "memory")

// ---------------- prep kernels ----------------

__global__ __launch_bounds__(256)
void prep_a_kernel(const float* __restrict__ A, size_t total4)
{
    size_t e = (size_t)blockIdx.x * 256 + threadIdx.x;
    if (e >= total4) return;
    float4 v = *(const float4*)(A + e * 4);
    uint2 o;
    o.x = pack_h2(v.x, v.y);
    o.y = pack_h2(v.z, v.w);
    *(uint2*)(gA + e * 2) = o;
}

__global__ __launch_bounds__(256)
void prep_w_kernel(const int* __restrict__ Q,
                   const float* __restrict__ S,
                   const int* __restrict__ Z,
                   int K, int NB, size_t total4)
{
    size_t e = (size_t)blockIdx.x * 256 + threadIdx.x;
    if (e >= total4) return;
    size_t base = e * 4;
    int n  = (int)(base / K);
    int k  = (int)(base % K);
    int kb = k >> 6;                 // BLOCK_SIZE=64; 4 consecutive k share kb
    float s  = S[(size_t)n * NB + kb];
    float nz = -(float)Z[(size_t)n * NB + kb] * s;
    int4 q = *(const int4*)(Q + base);
    uint2 o;
    o.x = pack_h2(fmaf((float)q.x, s, nz), fmaf((float)q.y, s, nz));
    o.y = pack_h2(fmaf((float)q.z, s, nz), fmaf((float)q.w, s, nz));
    *(uint2*)(gW + e * 2) = o;
}

// ---------------- GEMM kernel ----------------

__global__ __launch_bounds__(NTHREADS, 2)
void blkq4_gemm_f16(const float* __restrict__ bias,
                    float* __restrict__ C,
                    int M, int N, int K)
{
    extern __shared__ uint32_t smem[];

    const int tid  = threadIdx.x;
    const int lane = tid & 31;
    const int wid  = tid >> 5;        // 0..3
    const int warp_m = wid & 1;       // 0..1 -> 64-row slice
    const int warp_n = wid >> 1;      // 0..1 -> 64-col slice
    const int gid = lane >> 2;        // 0..7
    const int tig = lane & 3;         // 0..3

    const int bm = blockIdx.x;        // transposed grid: CTAs share gW block
    const int bn = blockIdx.y;

    const int Kw = K / 2;             // row stride of gA/gW in words
    const uint32_t* Ablk = gA + (size_t)bm * BM * Kw;
    const uint32_t* Wblk = gW + (size_t)bn * BN * Kw;

    const uint32_t sbase = (uint32_t)__cvta_generic_to_shared(smem);

    // cp.async: per operand 128 rows x 8 chunks(16B) = 1024; 8/thread each.
    // chunk id = tid + i*128: r = id>>3, word col = (id&7)*4
    const int cw_ld = (tid & 7) << 2;
    int r_ld[8];
    #pragma unroll
    for (int i = 0; i < 8; i++) r_ld[i] = (tid + i * 128) >> 3;

    // ldmatrix addressing
    const int lrow  = lane & 15;              // row within 16-row group
    const int lcolw = (lane >> 4) << 2;       // +0 or +4 words (k-lo/k-hi)
    uint32_t aOff[4], bOff[4];
    #pragma unroll
    for (int mi = 0; mi < 4; mi++)
        aOff[mi] = (uint32_t)(((warp_m * 64 + mi * 16 + lrow) * SSTRIDE + lcolw) * 4);
    #pragma unroll
    for (int n2 = 0; n2 < 4; n2++)
        bOff[n2] = (uint32_t)(((warp_n * 64 + n2 * 16 + lrow) * SSTRIDE + lcolw) * 4
                              + BM * SSTRIDE * 4);

    float acc[4][8][4];
    #pragma unroll
    for (int mi = 0; mi < 4; mi++)
        #pragma unroll
        for (int ni = 0; ni < 8; ni++)
            #pragma unroll
            for (int r = 0; r < 4; r++) acc[mi][ni][r] = 0.0f;

    const int T = K / BK;             // 64 tiles

    // ---- prologue: fill stages 0..STAGES-2 ----
    #pragma unroll
    for (int t = 0; t < STAGES - 1; t++) {
        const uint32_t aS = sbase + (t * STAGE_WORDS) * 4;
        const uint32_t wS = aS + (BM * SSTRIDE) * 4;
        const int k0w = t * KW;
        #pragma unroll
        for (int i = 0; i < 8; i++) {
            uint32_t doff = (uint32_t)(r_ld[i] * SSTRIDE + cw_ld) * 4;
            CP_ASYNC16(aS + doff, Ablk + (size_t)r_ld[i] * Kw + k0w + cw_ld);
            CP_ASYNC16(wS + doff, Wblk + (size_t)r_ld[i] * Kw + k0w + cw_ld);
        }
        CP_COMMIT();
    }

    for (int t = 0; t < T; t++) {
        CP_WAIT(STAGES - 2);          // tile t resident
        __syncthreads();              // all warps done reading tile t-1

        // ---- refill stage for tile t+STAGES-1 ----
        const int tl = t + STAGES - 1;
        if (tl < T) {
            const int sl = tl % STAGES;
            const uint32_t aS = sbase + (sl * STAGE_WORDS) * 4;
            const uint32_t wS = aS + (BM * SSTRIDE) * 4;
            const int k0w = tl * KW;
            #pragma unroll
            for (int i = 0; i < 8; i++) {
                uint32_t doff = (uint32_t)(r_ld[i] * SSTRIDE + cw_ld) * 4;
                CP_ASYNC16(aS + doff, Ablk + (size_t)r_ld[i] * Kw + k0w + cw_ld);
                CP_ASYNC16(wS + doff, Wblk + (size_t)r_ld[i] * Kw + k0w + cw_ld);
            }
        }
        CP_COMMIT();

        // ---- compute tile t: 4 k16 steps, fragment double-buffered ----
        const uint32_t stg = sbase + ((t % STAGES) * STAGE_WORDS) * 4;

        uint32_t af[2][4][4];
        uint32_t bf[2][8][2];

        // preload k-step 0 into buffer 0
        #pragma unroll
        for (int mi = 0; mi < 4; mi++)
            LDSM_X4(af[0][mi][0], af[0][mi][1], af[0][mi][2], af[0][mi][3],
                    stg + aOff[mi]);
        #pragma unroll
        for (int n2 = 0; n2 < 4; n2++)
            LDSM_X4(bf[0][2 * n2][0], bf[0][2 * n2 + 1][0],
                    bf[0][2 * n2][1], bf[0][2 * n2 + 1][1], stg + bOff[n2]);

        #pragma unroll
        for (int kk = 0; kk < 4; kk++) {
            const int cur = kk & 1;
            const int nxt = cur ^ 1;

            // prefetch k-step kk+1 into the other buffer
            if (kk < 3) {
                const uint32_t kb = stg + (uint32_t)((kk + 1) * 32);  // +32B per k16
                #pragma unroll
                for (int mi = 0; mi < 4; mi++)
                    LDSM_X4(af[nxt][mi][0], af[nxt][mi][1], af[nxt][mi][2], af[nxt][mi][3],
                            kb + aOff[mi]);
                #pragma unroll
                for (int n2 = 0; n2 < 4; n2++)
                    LDSM_X4(bf[nxt][2 * n2][0], bf[nxt][2 * n2 + 1][0],
                            bf[nxt][2 * n2][1], bf[nxt][2 * n2 + 1][1], kb + bOff[n2]);
            }

            #pragma unroll
            for (int mi = 0; mi < 4; mi++)
                #pragma unroll
                for (int ni = 0; ni < 8; ni++)
                    mma_f16(acc[mi][ni][0], acc[mi][ni][1], acc[mi][ni][2], acc[mi][ni][3],
                            af[cur][mi][0], af[cur][mi][1], af[cur][mi][2], af[cur][mi][3],
                            bf[cur][ni][0], bf[cur][ni][1]);
        }
    }

    // ---- epilogue ----
    #pragma unroll
    for (int mi = 0; mi < 4; mi++) {
        int row0 = bm * BM + warp_m * 64 + mi * 16 + gid;
        #pragma unroll
        for (int ni = 0; ni < 8; ni++) {
            int col = bn * BN + warp_n * 64 + ni * 8 + tig * 2;
            float2 bv = *(const float2*)(bias + col);
            float2 v0, v1;
            v0.x = acc[mi][ni][0] + bv.x;
            v0.y = acc[mi][ni][1] + bv.y;
            v1.x = acc[mi][ni][2] + bv.x;
            v1.y = acc[mi][ni][3] + bv.y;
            *(float2*)(C + (size_t)row0 * N + col)       = v0;
            *(float2*)(C + (size_t)(row0 + 8) * N + col) = v1;
        }
    }
}

extern "C" void kernel_launch(void* const* d_in, const int* in_sizes, int n_in,
                              void* d_out, int out_size)
{
    const float* A    = (const float*)d_in[0];   // input  [M,K]
    const int*   Q    = (const int*)  d_in[1];   // q_weights [N,K]
    const float* S    = (const float*)d_in[2];   // q_scales  [N,NB]
    const int*   Z    = (const int*)  d_in[3];   // q_zp      [N,NB]
    const float* bias = (const float*)d_in[4];   // [N]
    float*       C    = (float*)d_out;           // [M,N]

    const int N  = in_sizes[4];
    const int K  = in_sizes[1] / N;
    const int M  = in_sizes[0] / K;
    const int NB = in_sizes[2] / N;

    size_t a4 = (size_t)M * K / 4;
    size_t w4 = (size_t)N * K / 4;
    prep_a_kernel<<<(unsigned)((a4 + 255) / 256), 256>>>(A, a4);
    prep_w_kernel<<<(unsigned)((w4 + 255) / 256), 256>>>(Q, S, Z, K, NB, w4);

    cudaFuncSetAttribute(blkq4_gemm_f16,
                         cudaFuncAttributeMaxDynamicSharedMemorySize, SMEM_BYTES);

    dim3 grid(M / BM, N / BN);
    blkq4_gemm_f16<<<grid, NTHREADS, SMEM_BYTES>>>(bias, C, M, N, K);
}

// round 17
// speedup vs baseline: 1.6536x; 1.6536x over previous
#include <cuda_runtime.h>
#include <cuda_fp16.h>
#include <cstdint>

// Blockwise int4-dequant GEMM, fp16 mma.sync m16n8k16 + ldmatrix.x4.
// Round 17: R13 shape (128x128x64 CTA, 8 warps, warp tile 64x32, 2 CTA/SM,
// 3 stages, transposed grid) with the block-wide CP_WAIT+__syncthreads
// pipeline replaced by per-stage mbarrier full/empty pairs:
//   full[s]:  count 256, signaled by cp.async.mbarrier.arrive.noinc
//   empty[s]: count 256, signaled by mbarrier.arrive after compute
// No barrier in the main loop -> warps drift up to ~3 tiles, overlapping
// ldmatrix (crossbar) and HMMA (tensor) phases across warps.
//
// Phase 1: prep A -> fp16, W=(Q-zp)*s -> fp16 (global scratch).

#define M_DIM 4096
#define K_DIM 4096
#define N_DIM 11008

__device__ uint32_t gA[(size_t)M_DIM * K_DIM / 2];   // half2-packed A [M, K/2]
__device__ uint32_t gW[(size_t)N_DIM * K_DIM / 2];   // half2-packed W [N, K/2]

#define BM 128
#define BN 128
#define BK 64                        // k elements per tile (32 half2 words)
#define KW 32                        // words per row per tile
#define SSTRIDE 36                   // words per smem row (32 + 4 pad)
#define STAGES 3
#define STAGE_WORDS ((BM + BN) * SSTRIDE)
#define STAGE_BYTES (STAGE_WORDS * 4)
#define SMEM_STG 128                 // stages start after mbarriers
#define SMEM_BYTES (SMEM_STG + STAGES * STAGE_BYTES)

// mbarrier offsets: full[s] at s*16, empty[s] at s*16+8
#define MB_FULL(s)  ((s) * 16)
#define MB_EMPTY(s) ((s) * 16 + 8)

__device__ __forceinline__ uint32_t pack_h2(float lo, float hi) {
    uint32_t r;
    asm("{\n\t.reg .f16 l, h;\n\t"
        "cvt.rn.f16.f32 l, %1;\n\t"
        "cvt.rn.f16.f32 h, %2;\n\t"
        "mov.b32 %0, {l, h};\n\t}"
        : "=r"(r) : "f"(lo), "f"(hi));
    return r;
}

__device__ __forceinline__ void mma_f16(float& c0, float& c1, float& c2, float& c3,
                                        uint32_t a0, uint32_t a1, uint32_t a2, uint32_t a3,
                                        uint32_t b0, uint32_t b1) {
    asm volatile("mma.sync.aligned.m16n8k16.row.col.f32.f16.f16.f32 "
                 "{%0,%1,%2,%3}, {%4,%5,%6,%7}, {%8,%9}, {%0,%1,%2,%3};\n"
                 : "+f"(c0), "+f"(c1), "+f"(c2), "+f"(c3)
                 : "r"(a0), "r"(a1), "r"(a2), "r"(a3), "r"(b0), "r"(b1));
}

#define LDSM_X4(r0, r1, r2, r3, addr)                                        \
    asm volatile("ldmatrix.sync.aligned.m8n8.x4.shared.b16 {%0,%1,%2,%3}, [%4];" \
                 : "=r"(r0), "=r"(r1), "=r"(r2), "=r"(r3) : "r"(addr))

#define CP_ASYNC16(dst, src) \
    asm volatile("cp.async.cg.shared.global [%0], [%1], 16;" :: "r"(dst), "l"(src))

#define CP_MBAR_ARRIVE(addr) \
    asm volatile("cp.async.mbarrier.arrive.noinc.shared.b64 [%0];" :: "r"(addr) : "memory")

#define MBAR_INIT(addr, cnt) \
    asm volatile("mbarrier.init.shared.b64 [%0], %1;" :: "r"(addr), "r"(cnt) : "memory")

#define MBAR_ARRIVE(addr) \
    asm volatile("mbarrier.arrive.shared.b64 _, [%0];" :: "r"(addr) : "memory")

#define MBAR_WAIT(addr, ph) do {                                              \
    uint32_t _done;                                                           \
    asm volatile("{\n\t.reg .pred p;\n\t"                                     \
        "mbarrier.try_wait.parity.acquire.cta.shared::cta.b64 p, [%1], %2;\n\t" \
        "selp.b32 %0, 1, 0, p;\n\t}"                                          \
        : "=r"(_done) : "r"(addr), "r"((uint32_t)(ph)) : "memory");           \
    while (!_done) {                                                          \
        asm volatile("{\n\t.reg .pred p;\n\t"                                 \
            "mbarrier.try_wait.parity.acquire.cta.shared::cta.b64 p, [%1], %2, 0x989680;\n\t" \
            "selp.b32 %0, 1, 0, p;\n\t}"                                      \
            : "=r"(_done) : "r"(addr), "r"((uint32_t)(ph)) : "memory");       \
    }                                                                         \
} while (0)

// ---------------- prep kernels ----------------

__global__ __launch_bounds__(256)
void prep_a_kernel(const float* __restrict__ A, size_t total4)
{
    size_t e = (size_t)blockIdx.x * 256 + threadIdx.x;
    if (e >= total4) return;
    float4 v = *(const float4*)(A + e * 4);
    uint2 o;
    o.x = pack_h2(v.x, v.y);
    o.y = pack_h2(v.z, v.w);
    *(uint2*)(gA + e * 2) = o;
}

__global__ __launch_bounds__(256)
void prep_w_kernel(const int* __restrict__ Q,
                   const float* __restrict__ S,
                   const int* __restrict__ Z,
                   int K, int NB, size_t total4)
{
    size_t e = (size_t)blockIdx.x * 256 + threadIdx.x;
    if (e >= total4) return;
    size_t base = e * 4;
    int n  = (int)(base / K);
    int k  = (int)(base % K);
    int kb = k >> 6;                 // BLOCK_SIZE=64; 4 consecutive k share kb
    float s  = S[(size_t)n * NB + kb];
    float nz = -(float)Z[(size_t)n * NB + kb] * s;
    int4 q = *(const int4*)(Q + base);
    uint2 o;
    o.x = pack_h2(fmaf((float)q.x, s, nz), fmaf((float)q.y, s, nz));
    o.y = pack_h2(fmaf((float)q.z, s, nz), fmaf((float)q.w, s, nz));
    *(uint2*)(gW + e * 2) = o;
}

// ---------------- GEMM kernel ----------------

__global__ __launch_bounds__(256, 2)
void blkq4_gemm_f16(const float* __restrict__ bias,
                    float* __restrict__ C,
                    int M, int N, int K)
{
    extern __shared__ uint32_t smem[];

    const int tid  = threadIdx.x;
    const int lane = tid & 31;
    const int wid  = tid >> 5;
    const int warp_m = wid & 1;   // 0..1 -> 64-row half
    const int warp_n = wid >> 1;  // 0..3 -> 32-col slice
    const int gid = lane >> 2;    // 0..7
    const int tig = lane & 3;     // 0..3

    const int bm = blockIdx.x;    // transposed grid: consecutive CTAs share gW
    const int bn = blockIdx.y;

    const int Kw = K / 2;         // row stride of gA/gW in words
    const uint32_t* Ablk = gA + (size_t)bm * BM * Kw;
    const uint32_t* Wblk = gW + (size_t)bn * BN * Kw;

    const uint32_t sbase = (uint32_t)__cvta_generic_to_shared(smem);

    // ---- mbarrier init ----
    if (tid == 0) {
        #pragma unroll
        for (int s = 0; s < STAGES; s++) {
            MBAR_INIT(sbase + MB_FULL(s), 256);
            MBAR_INIT(sbase + MB_EMPTY(s), 256);
        }
    }
    __syncthreads();

    // cp.async slots: per operand 128 rows x 8 chunks(16B) = 1024; 4/thread.
    // chunk id = tid + i*256: r = id>>3, word col = (id&7)*4
    const int cw_ld = (tid & 7) << 2;
    const int r_ld[4] = { tid >> 3, (tid + 256) >> 3, (tid + 512) >> 3, (tid + 768) >> 3 };

    // ldmatrix addressing
    const int lrow  = lane & 15;               // row within 16-row group
    const int lcolw = (lane >> 4) << 2;        // +0 or +4 words (k-lo/k-hi)
    uint32_t aOff[4], bOff[2];
    #pragma unroll
    for (int mi = 0; mi < 4; mi++)
        aOff[mi] = (uint32_t)(((warp_m * 64 + mi * 16 + lrow) * SSTRIDE + lcolw) * 4);
    #pragma unroll
    for (int n2 = 0; n2 < 2; n2++)
        bOff[n2] = (uint32_t)(((warp_n * 32 + n2 * 16 + lrow) * SSTRIDE + lcolw) * 4
                              + BM * SSTRIDE * 4);

    float acc[4][4][4];
    #pragma unroll
    for (int mi = 0; mi < 4; mi++)
        #pragma unroll
        for (int ni = 0; ni < 4; ni++)
            #pragma unroll
            for (int r = 0; r < 4; r++) acc[mi][ni][r] = 0.0f;

    const int T = K / BK;         // 64 tiles

    // ---- prologue: fill stages 0..STAGES-2 (tiles 0,1) ----
    #pragma unroll
    for (int t = 0; t < STAGES - 1; t++) {
        const uint32_t aS = sbase + SMEM_STG + t * STAGE_BYTES;
        const uint32_t wS = aS + (BM * SSTRIDE) * 4;
        const int k0w = t * KW;
        #pragma unroll
        for (int i = 0; i < 4; i++) {
            uint32_t doff = (uint32_t)(r_ld[i] * SSTRIDE + cw_ld) * 4;
            CP_ASYNC16(aS + doff, Ablk + (size_t)r_ld[i] * Kw + k0w + cw_ld);
            CP_ASYNC16(wS + doff, Wblk + (size_t)r_ld[i] * Kw + k0w + cw_ld);
        }
        CP_MBAR_ARRIVE(sbase + MB_FULL(t));
    }

    for (int t = 0; t < T; t++) {
        // ---- producer: tile t+2 into stage (t+2)%3 ----
        const int tl = t + STAGES - 1;
        if (tl < T) {
            const int sl = tl % STAGES;
            const int ul = tl / STAGES;
            if (ul >= 1) MBAR_WAIT(sbase + MB_EMPTY(sl), (ul - 1) & 1);
            const uint32_t aS = sbase + SMEM_STG + sl * STAGE_BYTES;
            const uint32_t wS = aS + (BM * SSTRIDE) * 4;
            const int k0w = tl * KW;
            #pragma unroll
            for (int i = 0; i < 4; i++) {
                uint32_t doff = (uint32_t)(r_ld[i] * SSTRIDE + cw_ld) * 4;
                CP_ASYNC16(aS + doff, Ablk + (size_t)r_ld[i] * Kw + k0w + cw_ld);
                CP_ASYNC16(wS + doff, Wblk + (size_t)r_ld[i] * Kw + k0w + cw_ld);
            }
            CP_MBAR_ARRIVE(sbase + MB_FULL(sl));
        }

        // ---- consumer: tile t from stage t%3 ----
        const int sc = t % STAGES;
        const int uc = t / STAGES;
        MBAR_WAIT(sbase + MB_FULL(sc), uc & 1);

        const uint32_t stg = sbase + SMEM_STG + sc * STAGE_BYTES;

        #pragma unroll
        for (int kk = 0; kk < 4; kk++) {
            const uint32_t kb = stg + (uint32_t)(kk * 32);   // +32B per k16

            uint32_t af[4][4];
            #pragma unroll
            for (int mi = 0; mi < 4; mi++)
                LDSM_X4(af[mi][0], af[mi][1], af[mi][2], af[mi][3], kb + aOff[mi]);

            uint32_t bf[4][2];
            #pragma unroll
            for (int n2 = 0; n2 < 2; n2++)
                LDSM_X4(bf[2 * n2][0], bf[2 * n2 + 1][0],
                        bf[2 * n2][1], bf[2 * n2 + 1][1], kb + bOff[n2]);

            #pragma unroll
            for (int mi = 0; mi < 4; mi++)
                #pragma unroll
                for (int ni = 0; ni < 4; ni++)
                    mma_f16(acc[mi][ni][0], acc[mi][ni][1], acc[mi][ni][2], acc[mi][ni][3],
                            af[mi][0], af[mi][1], af[mi][2], af[mi][3],
                            bf[ni][0], bf[ni][1]);
        }

        MBAR_ARRIVE(sbase + MB_EMPTY(sc));
    }

    // ---- epilogue ----
    #pragma unroll
    for (int mi = 0; mi < 4; mi++) {
        int row0 = bm * BM + warp_m * 64 + mi * 16 + gid;
        #pragma unroll
        for (int ni = 0; ni < 4; ni++) {
            int col = bn * BN + warp_n * 32 + ni * 8 + tig * 2;
            float2 bv = *(const float2*)(bias + col);
            float2 v0, v1;
            v0.x = acc[mi][ni][0] + bv.x;
            v0.y = acc[mi][ni][1] + bv.y;
            v1.x = acc[mi][ni][2] + bv.x;
            v1.y = acc[mi][ni][3] + bv.y;
            *(float2*)(C + (size_t)row0 * N + col)       = v0;
            *(float2*)(C + (size_t)(row0 + 8) * N + col) = v1;
        }
    }
}

extern "C" void kernel_launch(void* const* d_in, const int* in_sizes, int n_in,
                              void* d_out, int out_size)
{
    const float* A    = (const float*)d_in[0];   // input  [M,K]
    const int*   Q    = (const int*)  d_in[1];   // q_weights [N,K]
    const float* S    = (const float*)d_in[2];   // q_scales  [N,NB]
    const int*   Z    = (const int*)  d_in[3];   // q_zp      [N,NB]
    const float* bias = (const float*)d_in[4];   // [N]
    float*       C    = (float*)d_out;           // [M,N]

    const int N  = in_sizes[4];
    const int K  = in_sizes[1] / N;
    const int M  = in_sizes[0] / K;
    const int NB = in_sizes[2] / N;

    size_t a4 = (size_t)M * K / 4;
    size_t w4 = (size_t)N * K / 4;
    prep_a_kernel<<<(unsigned)((a4 + 255) / 256), 256>>>(A, a4);
    prep_w_kernel<<<(unsigned)((w4 + 255) / 256), 256>>>(Q, S, Z, K, NB, w4);

    cudaFuncSetAttribute(blkq4_gemm_f16,
                         cudaFuncAttributeMaxDynamicSharedMemorySize, SMEM_BYTES);

    dim3 grid(M / BM, N / BN);
    blkq4_gemm_f16<<<grid, 256, SMEM_BYTES>>>(bias, C, M, N, K);
}